// round 1
// baseline (speedup 1.0000x reference)
#include <cuda_runtime.h>
#include <math.h>

// ---------------------------------------------------------------------------
// Problem dims (fixed by the dataset)
// ---------------------------------------------------------------------------
#define B_MAX   32768
#define CIN     512
#define H1      2048
#define H2      1024
#define COUT    256
#define PDIM    8

// ---------------------------------------------------------------------------
// Scratch (static __device__ arrays: the sanctioned no-alloc workaround)
// ---------------------------------------------------------------------------
__device__ float g_hid_w1[B_MAX * 32];
__device__ float g_hid_b1[B_MAX * 32];
__device__ float g_hid_w2[B_MAX * 32];
__device__ float g_hid_b2[B_MAX * 32];
__device__ float g_w1[(size_t)B_MAX * H1];
__device__ float g_b1[(size_t)B_MAX * H1];
__device__ float g_w2[(size_t)B_MAX * H2];
__device__ float g_b2[(size_t)B_MAX * H2];
__device__ float g_x1[(size_t)B_MAX * H1];
__device__ float g_x2[(size_t)B_MAX * H2];
__device__ float g_x3[(size_t)B_MAX * COUT];

// ---------------------------------------------------------------------------
// Hypernet hidden layer: H = relu(P @ W + b), P:[B,8], W:[8,32], H:[B,32]
// ---------------------------------------------------------------------------
__global__ __launch_bounds__(256) void hyper_hidden(
    const float* __restrict__ P, const float* __restrict__ W,
    const float* __restrict__ bias, float* __restrict__ H, int B)
{
    int idx = blockIdx.x * blockDim.x + threadIdx.x;
    int row = idx >> 5;
    int j = idx & 31;
    if (row >= B) return;
    float s = bias[j];
#pragma unroll
    for (int k = 0; k < PDIM; k++)
        s += P[row * PDIM + k] * W[k * 32 + j];
    H[(size_t)row * 32 + j] = fmaxf(s, 0.0f);
}

// ---------------------------------------------------------------------------
// Register-blocked SGEMM with bias:  C[M,N] = A[M,K] @ W[K,N] + bias[N]
// BM=128, BN=128, BK=8, TM=8, TN=8, 256 threads.
// Requires M%128==0, N%128==0 (or N==256 -> grid.x=2), K%8==0, K%4==0.
// ---------------------------------------------------------------------------
#define BM 128
#define BN 128
#define BK 8
#define TM 8
#define TN 8

__global__ __launch_bounds__(256) void sgemm_bias(
    int M, int N, int K,
    const float* __restrict__ A, const float* __restrict__ Bw,
    const float* __restrict__ bias, float* __restrict__ C)
{
    const int cRow = blockIdx.y;
    const int cCol = blockIdx.x;
    const int tid = threadIdx.x;

    const int threadCol = tid % (BN / TN);  // 0..15
    const int threadRow = tid / (BN / TN);  // 0..15

    __shared__ float As[BK * BM];
    __shared__ float Bs[BK * BN];

    const float* Ap = A + (size_t)cRow * BM * K;
    const float* Bp = Bw + cCol * BN;

    const int innerRowA = tid / (BK / 4);   // 0..127
    const int innerColA = tid % (BK / 4);   // 0..1
    const int innerRowB = tid / (BN / 4);   // 0..7
    const int innerColB = tid % (BN / 4);   // 0..31

    float acc[TM * TN];
#pragma unroll
    for (int i = 0; i < TM * TN; i++) acc[i] = 0.0f;
    float regM[TM], regN[TN];

    for (int bk = 0; bk < K; bk += BK) {
        float4 tA = *(const float4*)(&Ap[(size_t)innerRowA * K + innerColA * 4]);
        As[(innerColA * 4 + 0) * BM + innerRowA] = tA.x;
        As[(innerColA * 4 + 1) * BM + innerRowA] = tA.y;
        As[(innerColA * 4 + 2) * BM + innerRowA] = tA.z;
        As[(innerColA * 4 + 3) * BM + innerRowA] = tA.w;
        *(float4*)(&Bs[innerRowB * BN + innerColB * 4]) =
            *(const float4*)(&Bp[(size_t)innerRowB * N + innerColB * 4]);
        __syncthreads();
        Ap += BK;
        Bp += (size_t)BK * N;
#pragma unroll
        for (int dot = 0; dot < BK; ++dot) {
#pragma unroll
            for (int i = 0; i < TM; i++) regM[i] = As[dot * BM + threadRow * TM + i];
#pragma unroll
            for (int i = 0; i < TN; i++) regN[i] = Bs[dot * BN + threadCol * TN + i];
#pragma unroll
            for (int m = 0; m < TM; m++)
#pragma unroll
                for (int n = 0; n < TN; n++)
                    acc[m * TN + n] = fmaf(regM[m], regN[n], acc[m * TN + n]);
        }
        __syncthreads();
    }

#pragma unroll
    for (int m = 0; m < TM; m++) {
        size_t row = (size_t)cRow * BM + threadRow * TM + m;
#pragma unroll
        for (int n = 0; n < TN; n += 4) {
            int col = cCol * BN + threadCol * TN + n;
            float4 o;
            o.x = acc[m * TN + n + 0] + bias[col + 0];
            o.y = acc[m * TN + n + 1] + bias[col + 1];
            o.z = acc[m * TN + n + 2] + bias[col + 2];
            o.w = acc[m * TN + n + 3] + bias[col + 3];
            *(float4*)(&C[row * N + col]) = o;
        }
    }
}

// ---------------------------------------------------------------------------
// Per-sample groupnorm (n_group=1) + per-sample affine + ReLU, in place.
// One row per block, 256 threads.
// ---------------------------------------------------------------------------
__device__ __forceinline__ float warpReduceSum(float v)
{
#pragma unroll
    for (int o = 16; o > 0; o >>= 1) v += __shfl_xor_sync(0xffffffffu, v, o);
    return v;
}

template <int C>
__global__ __launch_bounds__(256) void gn_affine_relu(
    float* __restrict__ x, const float* __restrict__ w, const float* __restrict__ b)
{
    constexpr int PER = C / 256;
    const int row = blockIdx.x;
    const int tid = threadIdx.x;
    const size_t base = (size_t)row * C;

    float v[PER];
    float s = 0.0f, s2 = 0.0f;
#pragma unroll
    for (int i = 0; i < PER; i++) {
        float t = x[base + tid + i * 256];
        v[i] = t;
        s += t;
        s2 += t * t;
    }

    __shared__ float sh[16];
    s = warpReduceSum(s);
    s2 = warpReduceSum(s2);
    int lane = tid & 31, wid = tid >> 5;
    if (lane == 0) { sh[wid] = s; sh[8 + wid] = s2; }
    __syncthreads();
    if (tid < 32) {
        float a = (lane < 8) ? sh[lane] : 0.0f;
        float c = (lane < 8) ? sh[8 + lane] : 0.0f;
        a = warpReduceSum(a);
        c = warpReduceSum(c);
        if (lane == 0) { sh[0] = a; sh[1] = c; }
    }
    __syncthreads();

    const float invC = 1.0f / (float)C;
    float mean = sh[0] * invC;
    float var = sh[1] * invC - mean * mean;
    float inv = rsqrtf(var + 1e-5f);

#pragma unroll
    for (int i = 0; i < PER; i++) {
        int c = tid + i * 256;
        float y = (v[i] - mean) * inv * w[base + c] + b[base + c];
        x[base + c] = fmaxf(y, 0.0f);
    }
}

// ---------------------------------------------------------------------------
// log_softmax over 256 columns, one row per block (256 threads).
// ---------------------------------------------------------------------------
__global__ __launch_bounds__(256) void logsoftmax256(
    const float* __restrict__ x, float* __restrict__ out)
{
    const int row = blockIdx.x;
    const int tid = threadIdx.x;
    const size_t base = (size_t)row * 256;
    float v = x[base + tid];

    __shared__ float shm[8];
    __shared__ float shs[8];

    float m = v;
#pragma unroll
    for (int o = 16; o > 0; o >>= 1) m = fmaxf(m, __shfl_xor_sync(0xffffffffu, m, o));
    if ((tid & 31) == 0) shm[tid >> 5] = m;
    __syncthreads();
    float mx = shm[0];
#pragma unroll
    for (int i = 1; i < 8; i++) mx = fmaxf(mx, shm[i]);

    float e = expf(v - mx);
    float se = warpReduceSum(e);
    if ((tid & 31) == 0) shs[tid >> 5] = se;
    __syncthreads();
    float tot = 0.0f;
#pragma unroll
    for (int i = 0; i < 8; i++) tot += shs[i];

    out[base + tid] = (v - mx) - logf(tot);
}

// ---------------------------------------------------------------------------
// kernel_launch
// ---------------------------------------------------------------------------
extern "C" void kernel_launch(void* const* d_in, const int* in_sizes, int n_in,
                              void* d_out, int out_size)
{
    const float* x_feature = (const float*)d_in[0];
    const float* x_param   = (const float*)d_in[1];
    const float* hw1_1_w   = (const float*)d_in[2];
    const float* hw1_1_b   = (const float*)d_in[3];
    const float* hw1_2_w   = (const float*)d_in[4];
    const float* hw1_2_b   = (const float*)d_in[5];
    const float* hb1_1_w   = (const float*)d_in[6];
    const float* hb1_1_b   = (const float*)d_in[7];
    const float* hb1_2_w   = (const float*)d_in[8];
    const float* hb1_2_b   = (const float*)d_in[9];
    const float* hw2_1_w   = (const float*)d_in[10];
    const float* hw2_1_b   = (const float*)d_in[11];
    const float* hw2_2_w   = (const float*)d_in[12];
    const float* hw2_2_b   = (const float*)d_in[13];
    const float* hb2_1_w   = (const float*)d_in[14];
    const float* hb2_1_b   = (const float*)d_in[15];
    const float* hb2_2_w   = (const float*)d_in[16];
    const float* hb2_2_b   = (const float*)d_in[17];
    const float* l1_w      = (const float*)d_in[18];
    const float* l1_b      = (const float*)d_in[19];
    const float* l2_w      = (const float*)d_in[20];
    const float* l2_b      = (const float*)d_in[21];
    const float* l3_w      = (const float*)d_in[22];
    const float* l3_b      = (const float*)d_in[23];

    const int B = in_sizes[0] / CIN;   // 32768

    // Resolve scratch symbol addresses (pure lookups; no allocation).
    float *p_hw1, *p_hb1, *p_hw2, *p_hb2;
    float *p_w1, *p_b1, *p_w2, *p_b2, *p_x1, *p_x2, *p_x3;
    cudaGetSymbolAddress((void**)&p_hw1, g_hid_w1);
    cudaGetSymbolAddress((void**)&p_hb1, g_hid_b1);
    cudaGetSymbolAddress((void**)&p_hw2, g_hid_w2);
    cudaGetSymbolAddress((void**)&p_hb2, g_hid_b2);
    cudaGetSymbolAddress((void**)&p_w1, g_w1);
    cudaGetSymbolAddress((void**)&p_b1, g_b1);
    cudaGetSymbolAddress((void**)&p_w2, g_w2);
    cudaGetSymbolAddress((void**)&p_b2, g_b2);
    cudaGetSymbolAddress((void**)&p_x1, g_x1);
    cudaGetSymbolAddress((void**)&p_x2, g_x2);
    cudaGetSymbolAddress((void**)&p_x3, g_x3);

    // 1) Hypernet hidden layers (4 tiny GEMMs with relu)
    {
        int threads = 256;
        int blocks = (B * 32 + threads - 1) / threads;
        hyper_hidden<<<blocks, threads>>>(x_param, hw1_1_w, hw1_1_b, p_hw1, B);
        hyper_hidden<<<blocks, threads>>>(x_param, hb1_1_w, hb1_1_b, p_hb1, B);
        hyper_hidden<<<blocks, threads>>>(x_param, hw2_1_w, hw2_1_b, p_hw2, B);
        hyper_hidden<<<blocks, threads>>>(x_param, hb2_1_w, hb2_1_b, p_hb2, B);
    }

    dim3 block(256);
    dim3 gridH1(H1 / BN, B / BM);
    dim3 gridH2(H2 / BN, B / BM);
    dim3 gridO(COUT / BN, B / BM);  // COUT=256 -> grid.x = 2

    // 2) Hypernet output layers -> per-sample affine params
    sgemm_bias<<<gridH1, block>>>(B, H1, 32, p_hw1, hw1_2_w, hw1_2_b, p_w1);
    sgemm_bias<<<gridH1, block>>>(B, H1, 32, p_hb1, hb1_2_w, hb1_2_b, p_b1);
    sgemm_bias<<<gridH2, block>>>(B, H2, 32, p_hw2, hw2_2_w, hw2_2_b, p_w2);
    sgemm_bias<<<gridH2, block>>>(B, H2, 32, p_hb2, hb2_2_w, hb2_2_b, p_b2);

    // 3) Base net
    sgemm_bias<<<gridH1, block>>>(B, H1, CIN, x_feature, l1_w, l1_b, p_x1);
    gn_affine_relu<H1><<<B, 256>>>(p_x1, p_w1, p_b1);
    sgemm_bias<<<gridH2, block>>>(B, H2, H1, p_x1, l2_w, l2_b, p_x2);
    gn_affine_relu<H2><<<B, 256>>>(p_x2, p_w2, p_b2);
    sgemm_bias<<<gridO, block>>>(B, COUT, H2, p_x2, l3_w, l3_b, p_x3);

    // 4) log_softmax -> output
    logsoftmax256<<<B, 256>>>(p_x3, (float*)d_out);
}

// round 3
// speedup vs baseline: 3.3307x; 3.3307x over previous
#include <cuda_runtime.h>
#include <cstdint>
#include <math.h>

// ---------------------------------------------------------------------------
// Problem dims (fixed by the dataset)
// ---------------------------------------------------------------------------
#define B_MAX   32768
#define CIN     512
#define H1      2048
#define H2      1024
#define COUT    256
#define PDIM    8

// ---------------------------------------------------------------------------
// Scratch (__device__ globals: the sanctioned no-alloc workaround)
// ---------------------------------------------------------------------------
__device__ float g_hid_w1[B_MAX * 32];
__device__ float g_hid_b1[B_MAX * 32];
__device__ float g_hid_w2[B_MAX * 32];
__device__ float g_hid_b2[B_MAX * 32];
__device__ float g_w1[(size_t)B_MAX * H1];
__device__ float g_b1[(size_t)B_MAX * H1];
__device__ float g_w2[(size_t)B_MAX * H2];
__device__ float g_b2[(size_t)B_MAX * H2];
__device__ float g_x1[(size_t)B_MAX * H1];
__device__ float g_x2[(size_t)B_MAX * H2];
__device__ float g_x3[(size_t)B_MAX * COUT];
__device__ float g_xf[(size_t)B_MAX * CIN];     // tf32-rounded x_feature
// transposed (and tf32-rounded) weights [N, K]
__device__ float g_l1wt[(size_t)H1 * CIN];
__device__ float g_l2wt[(size_t)H2 * H1];
__device__ float g_l3wt[(size_t)COUT * H2];
__device__ float g_hw12t[H1 * 32];
__device__ float g_hb12t[H1 * 32];
__device__ float g_hw22t[H2 * 32];
__device__ float g_hb22t[H2 * 32];

// ---------------------------------------------------------------------------
// Helpers (all architecture-portable PTX: sm_80+)
// ---------------------------------------------------------------------------
__device__ __forceinline__ float tf32r(float x)
{
    uint32_t u;
    asm("cvt.rna.tf32.f32 %0, %1;" : "=r"(u) : "f"(x));
    return __uint_as_float(u);
}

__device__ __forceinline__ uint32_t smem_u32(const void* p)
{
    uint32_t a;
    asm("{ .reg .u64 t; cvta.to.shared.u64 t, %1; cvt.u32.u64 %0, t; }"
        : "=r"(a) : "l"(p));
    return a;
}

__device__ __forceinline__ void cp_async16(uint32_t dst, const void* src)
{
    asm volatile("cp.async.cg.shared.global [%0], [%1], 16;"
                 :: "r"(dst), "l"(src));
}
__device__ __forceinline__ void cp_commit()
{
    asm volatile("cp.async.commit_group;" ::: "memory");
}
template <int N>
__device__ __forceinline__ void cp_wait()
{
    asm volatile("cp.async.wait_group %0;" :: "n"(N) : "memory");
}

// tf32 m16n8k8 mma, fp32 accumulate (portable since sm_80)
__device__ __forceinline__ void mma8(float* d, const uint32_t* a, const uint32_t* b)
{
    asm volatile(
        "mma.sync.aligned.m16n8k8.row.col.f32.tf32.tf32.f32 "
        "{%0,%1,%2,%3}, {%4,%5,%6,%7}, {%8,%9}, {%0,%1,%2,%3};"
        : "+f"(d[0]), "+f"(d[1]), "+f"(d[2]), "+f"(d[3])
        : "r"(a[0]), "r"(a[1]), "r"(a[2]), "r"(a[3]), "r"(b[0]), "r"(b[1]));
}

// ---------------------------------------------------------------------------
// tf32 tensor-core GEMM:  C[M,N] = A[M,K] @ Bt[N,K]^T + bias[N]
// BM=BN=128, BK=32; 128 threads = 4 warps in 2x2 grid, 64x64 per warp.
// A and Bt must be pre-rounded to tf32. M%128==0, N%128==0, K%32==0.
// ---------------------------------------------------------------------------
#define BKT    32
#define LDT    36                       // padded row stride (floats)
#define TILE_F (128 * LDT)              // floats per tile per stage
#define GEMM_SMEM (2 * 2 * TILE_F * 4)  // 73728 bytes

__global__ __launch_bounds__(128, 2) void gemm_mma(
    int M, int N, int K,
    const float* __restrict__ A, const float* __restrict__ Bt,
    const float* __restrict__ bias, float* __restrict__ C)
{
    extern __shared__ float sm[];
    float* As = sm;                  // [2][128][LDT]
    float* Bs = sm + 2 * TILE_F;

    const int tid = threadIdx.x;
    const int lane = tid & 31, wid = tid >> 5;
    const int wm = wid & 1, wn = wid >> 1;      // 2x2 warp grid
    const int m0 = blockIdx.y * 128;
    const int n0 = blockIdx.x * 128;
    const int nkt = K / BKT;

    const float* Ag = A + (size_t)m0 * K;
    const float* Bg = Bt + (size_t)n0 * K;
    const uint32_t sA = smem_u32(As);
    const uint32_t sB = smem_u32(Bs);

    float acc[4][8][4];
#pragma unroll
    for (int mt = 0; mt < 4; mt++)
#pragma unroll
        for (int nt = 0; nt < 8; nt++)
#pragma unroll
            for (int j = 0; j < 4; j++) acc[mt][nt][j] = 0.0f;

    // ---- tile loader: 128 rows x 32 floats for A and B ----
    auto load_tiles = [&](int t) {
        const int s = t & 1;
        const uint32_t da = sA + s * (TILE_F * 4);
        const uint32_t db = sB + s * (TILE_F * 4);
        const float* ga = Ag + t * BKT;
        const float* gb = Bg + t * BKT;
#pragma unroll
        for (int it = 0; it < 8; it++) {
            int idx = tid + it * 128;
            int r = idx >> 3, c = idx & 7;
            uint32_t off = r * (LDT * 4) + c * 16;
            cp_async16(da + off, ga + (size_t)r * K + c * 4);
            cp_async16(db + off, gb + (size_t)r * K + c * 4);
        }
    };

    load_tiles(0);
    cp_commit();

    const int arow = lane >> 2;   // 0..7
    const int acol = lane & 3;    // 0..3

    for (int i = 0; i < nkt; i++) {
        if (i + 1 < nkt) {
            load_tiles(i + 1);
            cp_commit();
            cp_wait<1>();
        } else {
            cp_wait<0>();
        }
        __syncthreads();

        const int s = i & 1;
        const float* a = As + s * TILE_F + (wm * 64 + arow) * LDT + acol;
        const float* b = Bs + s * TILE_F + (wn * 64 + arow) * LDT + acol;

#pragma unroll
        for (int ks = 0; ks < 4; ks++) {
            uint32_t af[4][4], bf[8][2];
#pragma unroll
            for (int mt = 0; mt < 4; mt++) {
                const float* ap = a + mt * (16 * LDT) + ks * 8;
                af[mt][0] = __float_as_uint(ap[0]);
                af[mt][1] = __float_as_uint(ap[8 * LDT]);
                af[mt][2] = __float_as_uint(ap[4]);
                af[mt][3] = __float_as_uint(ap[8 * LDT + 4]);
            }
#pragma unroll
            for (int nt = 0; nt < 8; nt++) {
                const float* bp = b + nt * (8 * LDT) + ks * 8;
                bf[nt][0] = __float_as_uint(bp[0]);
                bf[nt][1] = __float_as_uint(bp[4]);
            }
#pragma unroll
            for (int mt = 0; mt < 4; mt++)
#pragma unroll
                for (int nt = 0; nt < 8; nt++)
                    mma8(acc[mt][nt], af[mt], bf[nt]);
        }
        __syncthreads();
    }

    // ---- epilogue: bias + store ----
    float2 bv[8];
#pragma unroll
    for (int nt = 0; nt < 8; nt++) {
        int cc = n0 + wn * 64 + nt * 8 + acol * 2;
        bv[nt] = *(const float2*)&bias[cc];
    }
#pragma unroll
    for (int mt = 0; mt < 4; mt++) {
        size_t r0 = (size_t)m0 + wm * 64 + mt * 16 + arow;
#pragma unroll
        for (int nt = 0; nt < 8; nt++) {
            int cc = n0 + wn * 64 + nt * 8 + acol * 2;
            float2 v0 = { acc[mt][nt][0] + bv[nt].x, acc[mt][nt][1] + bv[nt].y };
            float2 v1 = { acc[mt][nt][2] + bv[nt].x, acc[mt][nt][3] + bv[nt].y };
            *(float2*)&C[r0 * N + cc] = v0;
            *(float2*)&C[(r0 + 8) * N + cc] = v1;
        }
    }
}

// ---------------------------------------------------------------------------
// Weight transpose + tf32 round: src [K, N] -> dst [N, K]
// ---------------------------------------------------------------------------
__global__ void transpose_k(const float* __restrict__ src, float* __restrict__ dst,
                            int K, int N)
{
    __shared__ float t[32][33];
    int x = blockIdx.x * 32 + threadIdx.x;
    int y0 = blockIdx.y * 32;
#pragma unroll
    for (int j = 0; j < 32; j += 8)
        t[threadIdx.y + j][threadIdx.x] = src[(size_t)(y0 + threadIdx.y + j) * N + x];
    __syncthreads();
    int x2 = y0 + threadIdx.x;
    int y2 = blockIdx.x * 32 + threadIdx.y;
#pragma unroll
    for (int j = 0; j < 32; j += 8)
        dst[(size_t)(y2 + j) * K + x2] = tf32r(t[threadIdx.x][threadIdx.y + j]);
}

// ---------------------------------------------------------------------------
// Elementwise tf32 round (x_feature)
// ---------------------------------------------------------------------------
__global__ __launch_bounds__(256) void cvt_tf32_vec(
    const float* __restrict__ in, float* __restrict__ out, size_t n4)
{
    size_t i = (size_t)blockIdx.x * blockDim.x + threadIdx.x;
    if (i >= n4) return;
    float4 v = ((const float4*)in)[i];
    v.x = tf32r(v.x); v.y = tf32r(v.y); v.z = tf32r(v.z); v.w = tf32r(v.w);
    ((float4*)out)[i] = v;
}

// ---------------------------------------------------------------------------
// Hypernet hidden: H = tf32(relu(P @ W + b)), P:[B,8], W:[8,32]
// ---------------------------------------------------------------------------
__global__ __launch_bounds__(256) void hyper_hidden(
    const float* __restrict__ P, const float* __restrict__ W,
    const float* __restrict__ bias, float* __restrict__ H, int B)
{
    int idx = blockIdx.x * blockDim.x + threadIdx.x;
    int row = idx >> 5;
    int j = idx & 31;
    if (row >= B) return;
    float s = bias[j];
#pragma unroll
    for (int k = 0; k < PDIM; k++)
        s += P[row * PDIM + k] * W[k * 32 + j];
    H[(size_t)row * 32 + j] = tf32r(fmaxf(s, 0.0f));
}

// ---------------------------------------------------------------------------
// Per-sample groupnorm (n_group=1) + per-sample affine + ReLU (+tf32 round),
// in place. One row per block, 256 threads.
// ---------------------------------------------------------------------------
__device__ __forceinline__ float warpReduceSum(float v)
{
#pragma unroll
    for (int o = 16; o > 0; o >>= 1) v += __shfl_xor_sync(0xffffffffu, v, o);
    return v;
}

template <int C>
__global__ __launch_bounds__(256) void gn_affine_relu(
    float* __restrict__ x, const float* __restrict__ w, const float* __restrict__ b)
{
    constexpr int PER = C / 256;
    const int row = blockIdx.x;
    const int tid = threadIdx.x;
    const size_t base = (size_t)row * C;

    float v[PER];
    float s = 0.0f, s2 = 0.0f;
#pragma unroll
    for (int i = 0; i < PER; i++) {
        float t = x[base + tid + i * 256];
        v[i] = t;
        s += t;
        s2 += t * t;
    }

    __shared__ float sh[16];
    s = warpReduceSum(s);
    s2 = warpReduceSum(s2);
    int lane = tid & 31, wid = tid >> 5;
    if (lane == 0) { sh[wid] = s; sh[8 + wid] = s2; }
    __syncthreads();
    if (tid < 32) {
        float a = (lane < 8) ? sh[lane] : 0.0f;
        float c = (lane < 8) ? sh[8 + lane] : 0.0f;
        a = warpReduceSum(a);
        c = warpReduceSum(c);
        if (lane == 0) { sh[0] = a; sh[1] = c; }
    }
    __syncthreads();

    const float invC = 1.0f / (float)C;
    float mean = sh[0] * invC;
    float var = sh[1] * invC - mean * mean;
    float inv = rsqrtf(var + 1e-5f);

#pragma unroll
    for (int i = 0; i < PER; i++) {
        int c = tid + i * 256;
        float y = (v[i] - mean) * inv * w[base + c] + b[base + c];
        x[base + c] = tf32r(fmaxf(y, 0.0f));
    }
}

// ---------------------------------------------------------------------------
// log_softmax over 256 columns, one row per block (256 threads).
// ---------------------------------------------------------------------------
__global__ __launch_bounds__(256) void logsoftmax256(
    const float* __restrict__ x, float* __restrict__ out)
{
    const int row = blockIdx.x;
    const int tid = threadIdx.x;
    const size_t base = (size_t)row * 256;
    float v = x[base + tid];

    __shared__ float shm[8];
    __shared__ float shs[8];

    float m = v;
#pragma unroll
    for (int o = 16; o > 0; o >>= 1) m = fmaxf(m, __shfl_xor_sync(0xffffffffu, m, o));
    if ((tid & 31) == 0) shm[tid >> 5] = m;
    __syncthreads();
    float mx = shm[0];
#pragma unroll
    for (int i = 1; i < 8; i++) mx = fmaxf(mx, shm[i]);

    float e = expf(v - mx);
    float se = warpReduceSum(e);
    if ((tid & 31) == 0) shs[tid >> 5] = se;
    __syncthreads();
    float tot = 0.0f;
#pragma unroll
    for (int i = 0; i < 8; i++) tot += shs[i];

    out[base + tid] = (v - mx) - logf(tot);
}

// ---------------------------------------------------------------------------
// kernel_launch
// ---------------------------------------------------------------------------
extern "C" void kernel_launch(void* const* d_in, const int* in_sizes, int n_in,
                              void* d_out, int out_size)
{
    const float* x_feature = (const float*)d_in[0];
    const float* x_param   = (const float*)d_in[1];
    const float* hw1_1_w   = (const float*)d_in[2];
    const float* hw1_1_b   = (const float*)d_in[3];
    const float* hw1_2_w   = (const float*)d_in[4];
    const float* hw1_2_b   = (const float*)d_in[5];
    const float* hb1_1_w   = (const float*)d_in[6];
    const float* hb1_1_b   = (const float*)d_in[7];
    const float* hb1_2_w   = (const float*)d_in[8];
    const float* hb1_2_b   = (const float*)d_in[9];
    const float* hw2_1_w   = (const float*)d_in[10];
    const float* hw2_1_b   = (const float*)d_in[11];
    const float* hw2_2_w   = (const float*)d_in[12];
    const float* hw2_2_b   = (const float*)d_in[13];
    const float* hb2_1_w   = (const float*)d_in[14];
    const float* hb2_1_b   = (const float*)d_in[15];
    const float* hb2_2_w   = (const float*)d_in[16];
    const float* hb2_2_b   = (const float*)d_in[17];
    const float* l1_w      = (const float*)d_in[18];
    const float* l1_b      = (const float*)d_in[19];
    const float* l2_w      = (const float*)d_in[20];
    const float* l2_b      = (const float*)d_in[21];
    const float* l3_w      = (const float*)d_in[22];
    const float* l3_b      = (const float*)d_in[23];

    const int B = in_sizes[0] / CIN;   // 32768

    float *p_hw1, *p_hb1, *p_hw2, *p_hb2;
    float *p_w1, *p_b1, *p_w2, *p_b2, *p_x1, *p_x2, *p_x3, *p_xf;
    float *p_l1wt, *p_l2wt, *p_l3wt, *p_hw12t, *p_hb12t, *p_hw22t, *p_hb22t;
    cudaGetSymbolAddress((void**)&p_hw1, g_hid_w1);
    cudaGetSymbolAddress((void**)&p_hb1, g_hid_b1);
    cudaGetSymbolAddress((void**)&p_hw2, g_hid_w2);
    cudaGetSymbolAddress((void**)&p_hb2, g_hid_b2);
    cudaGetSymbolAddress((void**)&p_w1, g_w1);
    cudaGetSymbolAddress((void**)&p_b1, g_b1);
    cudaGetSymbolAddress((void**)&p_w2, g_w2);
    cudaGetSymbolAddress((void**)&p_b2, g_b2);
    cudaGetSymbolAddress((void**)&p_x1, g_x1);
    cudaGetSymbolAddress((void**)&p_x2, g_x2);
    cudaGetSymbolAddress((void**)&p_x3, g_x3);
    cudaGetSymbolAddress((void**)&p_xf, g_xf);
    cudaGetSymbolAddress((void**)&p_l1wt, g_l1wt);
    cudaGetSymbolAddress((void**)&p_l2wt, g_l2wt);
    cudaGetSymbolAddress((void**)&p_l3wt, g_l3wt);
    cudaGetSymbolAddress((void**)&p_hw12t, g_hw12t);
    cudaGetSymbolAddress((void**)&p_hb12t, g_hb12t);
    cudaGetSymbolAddress((void**)&p_hw22t, g_hw22t);
    cudaGetSymbolAddress((void**)&p_hb22t, g_hb22t);

    cudaFuncSetAttribute(gemm_mma, cudaFuncAttributeMaxDynamicSharedMemorySize,
                         GEMM_SMEM);

    dim3 tb(32, 8);
    // weight transposes (+tf32 round): src [K,N] -> dst [N,K]
    transpose_k<<<dim3(H1 / 32, CIN / 32), tb>>>(l1_w, p_l1wt, CIN, H1);
    transpose_k<<<dim3(H2 / 32, H1 / 32), tb>>>(l2_w, p_l2wt, H1, H2);
    transpose_k<<<dim3(COUT / 32, H2 / 32), tb>>>(l3_w, p_l3wt, H2, COUT);
    transpose_k<<<dim3(H1 / 32, 1), tb>>>(hw1_2_w, p_hw12t, 32, H1);
    transpose_k<<<dim3(H1 / 32, 1), tb>>>(hb1_2_w, p_hb12t, 32, H1);
    transpose_k<<<dim3(H2 / 32, 1), tb>>>(hw2_2_w, p_hw22t, 32, H2);
    transpose_k<<<dim3(H2 / 32, 1), tb>>>(hb2_2_w, p_hb22t, 32, H2);

    // x_feature -> tf32-rounded copy
    {
        size_t n4 = (size_t)B * CIN / 4;
        cvt_tf32_vec<<<(unsigned)((n4 + 255) / 256), 256>>>(x_feature, p_xf, n4);
    }

    // hypernet hidden layers
    {
        int blocks = (B * 32 + 255) / 256;
        hyper_hidden<<<blocks, 256>>>(x_param, hw1_1_w, hw1_1_b, p_hw1, B);
        hyper_hidden<<<blocks, 256>>>(x_param, hb1_1_w, hb1_1_b, p_hb1, B);
        hyper_hidden<<<blocks, 256>>>(x_param, hw2_1_w, hw2_1_b, p_hw2, B);
        hyper_hidden<<<blocks, 256>>>(x_param, hb2_1_w, hb2_1_b, p_hb2, B);
    }

    const int mg = B / 128;
    // hypernet output layers -> per-sample affine params
    gemm_mma<<<dim3(H1 / 128, mg), 128, GEMM_SMEM>>>(B, H1, 32, p_hw1, p_hw12t, hw1_2_b, p_w1);
    gemm_mma<<<dim3(H1 / 128, mg), 128, GEMM_SMEM>>>(B, H1, 32, p_hb1, p_hb12t, hb1_2_b, p_b1);
    gemm_mma<<<dim3(H2 / 128, mg), 128, GEMM_SMEM>>>(B, H2, 32, p_hw2, p_hw22t, hw2_2_b, p_w2);
    gemm_mma<<<dim3(H2 / 128, mg), 128, GEMM_SMEM>>>(B, H2, 32, p_hb2, p_hb22t, hb2_2_b, p_b2);

    // base net
    gemm_mma<<<dim3(H1 / 128, mg), 128, GEMM_SMEM>>>(B, H1, CIN, p_xf, p_l1wt, l1_b, p_x1);
    gn_affine_relu<H1><<<B, 256>>>(p_x1, p_w1, p_b1);
    gemm_mma<<<dim3(H2 / 128, mg), 128, GEMM_SMEM>>>(B, H2, H1, p_x1, p_l2wt, l2_b, p_x2);
    gn_affine_relu<H2><<<B, 256>>>(p_x2, p_w2, p_b2);
    gemm_mma<<<dim3(COUT / 128, mg), 128, GEMM_SMEM>>>(B, COUT, H2, p_x2, p_l3wt, l3_b, p_x3);

    // log_softmax -> output
    logsoftmax256<<<B, 256>>>(p_x3, (float*)d_out);
}

// round 4
// speedup vs baseline: 3.5724x; 1.0726x over previous
#include <cuda_runtime.h>
#include <cstdint>
#include <math.h>

// ---------------------------------------------------------------------------
// Problem dims (fixed by the dataset)
// ---------------------------------------------------------------------------
#define B_MAX   32768
#define CIN     512
#define H1      2048
#define H2      1024
#define COUT    256
#define PDIM    8

// ---------------------------------------------------------------------------
// Scratch (__device__ globals: the sanctioned no-alloc workaround)
// ---------------------------------------------------------------------------
__device__ float g_hid_w1[B_MAX * 32];
__device__ float g_hid_b1[B_MAX * 32];
__device__ float g_hid_w2[B_MAX * 32];
__device__ float g_hid_b2[B_MAX * 32];
__device__ float g_w1[(size_t)B_MAX * H1];
__device__ float g_b1[(size_t)B_MAX * H1];
__device__ float g_w2[(size_t)B_MAX * H2];
__device__ float g_b2[(size_t)B_MAX * H2];
__device__ float g_x1[(size_t)B_MAX * H1];
__device__ float g_x2[(size_t)B_MAX * H2];
__device__ float g_x3[(size_t)B_MAX * COUT];
__device__ float g_xf[(size_t)B_MAX * CIN];     // tf32-rounded x_feature
// transposed (and tf32-rounded) weights [N, K]
__device__ float g_l1wt[(size_t)H1 * CIN];
__device__ float g_l2wt[(size_t)H2 * H1];
__device__ float g_l3wt[(size_t)COUT * H2];
__device__ float g_hw12t[H1 * 32];
__device__ float g_hb12t[H1 * 32];
__device__ float g_hw22t[H2 * 32];
__device__ float g_hb22t[H2 * 32];

// ---------------------------------------------------------------------------
// Helpers (all architecture-portable PTX: sm_80+)
// ---------------------------------------------------------------------------
__device__ __forceinline__ float tf32r(float x)
{
    uint32_t u;
    asm("cvt.rna.tf32.f32 %0, %1;" : "=r"(u) : "f"(x));
    return __uint_as_float(u);
}

__device__ __forceinline__ uint32_t smem_u32(const void* p)
{
    uint32_t a;
    asm("{ .reg .u64 t; cvta.to.shared.u64 t, %1; cvt.u32.u64 %0, t; }"
        : "=r"(a) : "l"(p));
    return a;
}

__device__ __forceinline__ void cp_async16(uint32_t dst, const void* src)
{
    asm volatile("cp.async.cg.shared.global [%0], [%1], 16;"
                 :: "r"(dst), "l"(src));
}
__device__ __forceinline__ void cp_commit()
{
    asm volatile("cp.async.commit_group;" ::: "memory");
}
template <int N>
__device__ __forceinline__ void cp_wait()
{
    asm volatile("cp.async.wait_group %0;" :: "n"(N) : "memory");
}

// tf32 m16n8k8 mma, fp32 accumulate (portable since sm_80)
__device__ __forceinline__ void mma8(float* d, const uint32_t* a, const uint32_t* b)
{
    asm volatile(
        "mma.sync.aligned.m16n8k8.row.col.f32.tf32.tf32.f32 "
        "{%0,%1,%2,%3}, {%4,%5,%6,%7}, {%8,%9}, {%0,%1,%2,%3};"
        : "+f"(d[0]), "+f"(d[1]), "+f"(d[2]), "+f"(d[3])
        : "r"(a[0]), "r"(a[1]), "r"(a[2]), "r"(a[3]), "r"(b[0]), "r"(b[1]));
}

// ldmatrix x4 (portable since sm_75); on 32-bit data each m8n8.b16 matrix is
// an 8-row x 16-byte block = 8x4 floats.
__device__ __forceinline__ void ldsm4(uint32_t* r, uint32_t addr)
{
    asm volatile("ldmatrix.sync.aligned.m8n8.x4.shared.b16 {%0,%1,%2,%3}, [%4];"
                 : "=r"(r[0]), "=r"(r[1]), "=r"(r[2]), "=r"(r[3]) : "r"(addr));
}

// ---------------------------------------------------------------------------
// tf32 tensor-core GEMM:  C[M,N] = A[M,K] @ Bt[N,K]^T + bias[N]
// BM=BN=128, BK=32; 128 threads = 4 warps in 2x2 grid, 64x64 per warp.
// Fragments via ldmatrix.x4. A and Bt pre-rounded to tf32.
// M%128==0, N%128==0, K%32==0.
// ---------------------------------------------------------------------------
#define BKT    32
#define LDT    36                       // padded row stride (floats)
#define TILE_F (128 * LDT)              // floats per tile per stage
#define GEMM_SMEM (2 * 2 * TILE_F * 4)  // 73728 bytes

__global__ __launch_bounds__(128, 2) void gemm_mma(
    int M, int N, int K,
    const float* __restrict__ A, const float* __restrict__ Bt,
    const float* __restrict__ bias, float* __restrict__ C)
{
    extern __shared__ float sm[];
    float* As = sm;                  // [2][128][LDT]
    float* Bs = sm + 2 * TILE_F;

    const int tid = threadIdx.x;
    const int lane = tid & 31, wid = tid >> 5;
    const int wm = wid & 1, wn = wid >> 1;      // 2x2 warp grid
    const int m0 = blockIdx.y * 128;
    const int n0 = blockIdx.x * 128;
    const int nkt = K / BKT;

    const float* Ag = A + (size_t)m0 * K;
    const float* Bg = Bt + (size_t)n0 * K;
    const uint32_t sA = smem_u32(As);
    const uint32_t sB = smem_u32(Bs);

    // per-thread ldmatrix base offsets (bytes) within a tile
    // A: rows 0..15 from lanes 0..15 (repeated), k-half from lane>>4
    const uint32_t a_off =
        (uint32_t)(((wm * 64 + (lane & 15)) * LDT + ((lane >> 4) << 2)) * 4);
    // B: n-half from lane>>4 (8 rows), k-half from (lane>>3)&1
    const uint32_t b_off =
        (uint32_t)(((wn * 64 + ((lane >> 4) << 3) + (lane & 7)) * LDT +
                    (((lane >> 3) & 1) << 2)) * 4);

    float acc[4][8][4];
#pragma unroll
    for (int mt = 0; mt < 4; mt++)
#pragma unroll
        for (int nt = 0; nt < 8; nt++)
#pragma unroll
            for (int j = 0; j < 4; j++) acc[mt][nt][j] = 0.0f;

    // ---- tile loader: 128 rows x 32 floats for A and B ----
    auto load_tiles = [&](int t) {
        const int s = t & 1;
        const uint32_t da = sA + s * (TILE_F * 4);
        const uint32_t db = sB + s * (TILE_F * 4);
        const float* ga = Ag + t * BKT;
        const float* gb = Bg + t * BKT;
#pragma unroll
        for (int it = 0; it < 8; it++) {
            int idx = tid + it * 128;
            int r = idx >> 3, c = idx & 7;
            uint32_t off = r * (LDT * 4) + c * 16;
            cp_async16(da + off, ga + (size_t)r * K + c * 4);
            cp_async16(db + off, gb + (size_t)r * K + c * 4);
        }
    };

    load_tiles(0);
    cp_commit();

    const int arow = lane >> 2;   // 0..7 (for epilogue)
    const int acol = lane & 3;    // 0..3

    for (int i = 0; i < nkt; i++) {
        if (i + 1 < nkt) {
            load_tiles(i + 1);
            cp_commit();
            cp_wait<1>();
        } else {
            cp_wait<0>();
        }
        __syncthreads();

        const int s = i & 1;
        const uint32_t sa = sA + s * (TILE_F * 4) + a_off;
        const uint32_t sb = sB + s * (TILE_F * 4) + b_off;

#pragma unroll
        for (int ks = 0; ks < 4; ks++) {
            uint32_t af[4][4], bf[4][4];
#pragma unroll
            for (int mt = 0; mt < 4; mt++)
                ldsm4(af[mt], sa + (uint32_t)((mt * 16 * LDT + ks * 8) * 4));
#pragma unroll
            for (int np = 0; np < 4; np++)
                ldsm4(bf[np], sb + (uint32_t)((np * 16 * LDT + ks * 8) * 4));
#pragma unroll
            for (int mt = 0; mt < 4; mt++)
#pragma unroll
                for (int nt = 0; nt < 8; nt++)
                    mma8(acc[mt][nt], af[mt], bf[nt >> 1] + (nt & 1) * 2);
        }
        __syncthreads();
    }

    // ---- epilogue: bias + store ----
    float2 bv[8];
#pragma unroll
    for (int nt = 0; nt < 8; nt++) {
        int cc = n0 + wn * 64 + nt * 8 + acol * 2;
        bv[nt] = *(const float2*)&bias[cc];
    }
#pragma unroll
    for (int mt = 0; mt < 4; mt++) {
        size_t r0 = (size_t)m0 + wm * 64 + mt * 16 + arow;
#pragma unroll
        for (int nt = 0; nt < 8; nt++) {
            int cc = n0 + wn * 64 + nt * 8 + acol * 2;
            float2 v0 = { acc[mt][nt][0] + bv[nt].x, acc[mt][nt][1] + bv[nt].y };
            float2 v1 = { acc[mt][nt][2] + bv[nt].x, acc[mt][nt][3] + bv[nt].y };
            *(float2*)&C[r0 * N + cc] = v0;
            *(float2*)&C[(r0 + 8) * N + cc] = v1;
        }
    }
}

// ---------------------------------------------------------------------------
// Weight transpose + tf32 round: src [K, N] -> dst [N, K]
// ---------------------------------------------------------------------------
__global__ void transpose_k(const float* __restrict__ src, float* __restrict__ dst,
                            int K, int N)
{
    __shared__ float t[32][33];
    int x = blockIdx.x * 32 + threadIdx.x;
    int y0 = blockIdx.y * 32;
#pragma unroll
    for (int j = 0; j < 32; j += 8)
        t[threadIdx.y + j][threadIdx.x] = src[(size_t)(y0 + threadIdx.y + j) * N + x];
    __syncthreads();
    int x2 = y0 + threadIdx.x;
    int y2 = blockIdx.x * 32 + threadIdx.y;
#pragma unroll
    for (int j = 0; j < 32; j += 8)
        dst[(size_t)(y2 + j) * K + x2] = tf32r(t[threadIdx.x][threadIdx.y + j]);
}

// ---------------------------------------------------------------------------
// Elementwise tf32 round (x_feature)
// ---------------------------------------------------------------------------
__global__ __launch_bounds__(256) void cvt_tf32_vec(
    const float* __restrict__ in, float* __restrict__ out, size_t n4)
{
    size_t i = (size_t)blockIdx.x * blockDim.x + threadIdx.x;
    if (i >= n4) return;
    float4 v = ((const float4*)in)[i];
    v.x = tf32r(v.x); v.y = tf32r(v.y); v.z = tf32r(v.z); v.w = tf32r(v.w);
    ((float4*)out)[i] = v;
}

// ---------------------------------------------------------------------------
// Hypernet hidden: H = tf32(relu(P @ W + b)), P:[B,8], W:[8,32]
// ---------------------------------------------------------------------------
__global__ __launch_bounds__(256) void hyper_hidden(
    const float* __restrict__ P, const float* __restrict__ W,
    const float* __restrict__ bias, float* __restrict__ H, int B)
{
    int idx = blockIdx.x * blockDim.x + threadIdx.x;
    int row = idx >> 5;
    int j = idx & 31;
    if (row >= B) return;
    float s = bias[j];
#pragma unroll
    for (int k = 0; k < PDIM; k++)
        s += P[row * PDIM + k] * W[k * 32 + j];
    H[(size_t)row * 32 + j] = tf32r(fmaxf(s, 0.0f));
}

// ---------------------------------------------------------------------------
// Per-sample groupnorm (n_group=1) + per-sample affine + ReLU (+tf32 round),
// in place. One row per block, 256 threads.
// ---------------------------------------------------------------------------
__device__ __forceinline__ float warpReduceSum(float v)
{
#pragma unroll
    for (int o = 16; o > 0; o >>= 1) v += __shfl_xor_sync(0xffffffffu, v, o);
    return v;
}

template <int C>
__global__ __launch_bounds__(256) void gn_affine_relu(
    float* __restrict__ x, const float* __restrict__ w, const float* __restrict__ b)
{
    constexpr int PER = C / 256;
    const int row = blockIdx.x;
    const int tid = threadIdx.x;
    const size_t base = (size_t)row * C;

    float v[PER];
    float s = 0.0f, s2 = 0.0f;
#pragma unroll
    for (int i = 0; i < PER; i++) {
        float t = x[base + tid + i * 256];
        v[i] = t;
        s += t;
        s2 += t * t;
    }

    __shared__ float sh[16];
    s = warpReduceSum(s);
    s2 = warpReduceSum(s2);
    int lane = tid & 31, wid = tid >> 5;
    if (lane == 0) { sh[wid] = s; sh[8 + wid] = s2; }
    __syncthreads();
    if (tid < 32) {
        float a = (lane < 8) ? sh[lane] : 0.0f;
        float c = (lane < 8) ? sh[8 + lane] : 0.0f;
        a = warpReduceSum(a);
        c = warpReduceSum(c);
        if (lane == 0) { sh[0] = a; sh[1] = c; }
    }
    __syncthreads();

    const float invC = 1.0f / (float)C;
    float mean = sh[0] * invC;
    float var = sh[1] * invC - mean * mean;
    float inv = rsqrtf(var + 1e-5f);

#pragma unroll
    for (int i = 0; i < PER; i++) {
        int c = tid + i * 256;
        float y = (v[i] - mean) * inv * w[base + c] + b[base + c];
        x[base + c] = tf32r(fmaxf(y, 0.0f));
    }
}

// ---------------------------------------------------------------------------
// log_softmax over 256 columns, one row per block (256 threads).
// ---------------------------------------------------------------------------
__global__ __launch_bounds__(256) void logsoftmax256(
    const float* __restrict__ x, float* __restrict__ out)
{
    const int row = blockIdx.x;
    const int tid = threadIdx.x;
    const size_t base = (size_t)row * 256;
    float v = x[base + tid];

    __shared__ float shm[8];
    __shared__ float shs[8];

    float m = v;
#pragma unroll
    for (int o = 16; o > 0; o >>= 1) m = fmaxf(m, __shfl_xor_sync(0xffffffffu, m, o));
    if ((tid & 31) == 0) shm[tid >> 5] = m;
    __syncthreads();
    float mx = shm[0];
#pragma unroll
    for (int i = 1; i < 8; i++) mx = fmaxf(mx, shm[i]);

    float e = expf(v - mx);
    float se = warpReduceSum(e);
    if ((tid & 31) == 0) shs[tid >> 5] = se;
    __syncthreads();
    float tot = 0.0f;
#pragma unroll
    for (int i = 0; i < 8; i++) tot += shs[i];

    out[base + tid] = (v - mx) - logf(tot);
}

// ---------------------------------------------------------------------------
// kernel_launch
// ---------------------------------------------------------------------------
extern "C" void kernel_launch(void* const* d_in, const int* in_sizes, int n_in,
                              void* d_out, int out_size)
{
    const float* x_feature = (const float*)d_in[0];
    const float* x_param   = (const float*)d_in[1];
    const float* hw1_1_w   = (const float*)d_in[2];
    const float* hw1_1_b   = (const float*)d_in[3];
    const float* hw1_2_w   = (const float*)d_in[4];
    const float* hw1_2_b   = (const float*)d_in[5];
    const float* hb1_1_w   = (const float*)d_in[6];
    const float* hb1_1_b   = (const float*)d_in[7];
    const float* hb1_2_w   = (const float*)d_in[8];
    const float* hb1_2_b   = (const float*)d_in[9];
    const float* hw2_1_w   = (const float*)d_in[10];
    const float* hw2_1_b   = (const float*)d_in[11];
    const float* hw2_2_w   = (const float*)d_in[12];
    const float* hw2_2_b   = (const float*)d_in[13];
    const float* hb2_1_w   = (const float*)d_in[14];
    const float* hb2_1_b   = (const float*)d_in[15];
    const float* hb2_2_w   = (const float*)d_in[16];
    const float* hb2_2_b   = (const float*)d_in[17];
    const float* l1_w      = (const float*)d_in[18];
    const float* l1_b      = (const float*)d_in[19];
    const float* l2_w      = (const float*)d_in[20];
    const float* l2_b      = (const float*)d_in[21];
    const float* l3_w      = (const float*)d_in[22];
    const float* l3_b      = (const float*)d_in[23];

    const int B = in_sizes[0] / CIN;   // 32768

    float *p_hw1, *p_hb1, *p_hw2, *p_hb2;
    float *p_w1, *p_b1, *p_w2, *p_b2, *p_x1, *p_x2, *p_x3, *p_xf;
    float *p_l1wt, *p_l2wt, *p_l3wt, *p_hw12t, *p_hb12t, *p_hw22t, *p_hb22t;
    cudaGetSymbolAddress((void**)&p_hw1, g_hid_w1);
    cudaGetSymbolAddress((void**)&p_hb1, g_hid_b1);
    cudaGetSymbolAddress((void**)&p_hw2, g_hid_w2);
    cudaGetSymbolAddress((void**)&p_hb2, g_hid_b2);
    cudaGetSymbolAddress((void**)&p_w1, g_w1);
    cudaGetSymbolAddress((void**)&p_b1, g_b1);
    cudaGetSymbolAddress((void**)&p_w2, g_w2);
    cudaGetSymbolAddress((void**)&p_b2, g_b2);
    cudaGetSymbolAddress((void**)&p_x1, g_x1);
    cudaGetSymbolAddress((void**)&p_x2, g_x2);
    cudaGetSymbolAddress((void**)&p_x3, g_x3);
    cudaGetSymbolAddress((void**)&p_xf, g_xf);
    cudaGetSymbolAddress((void**)&p_l1wt, g_l1wt);
    cudaGetSymbolAddress((void**)&p_l2wt, g_l2wt);
    cudaGetSymbolAddress((void**)&p_l3wt, g_l3wt);
    cudaGetSymbolAddress((void**)&p_hw12t, g_hw12t);
    cudaGetSymbolAddress((void**)&p_hb12t, g_hb12t);
    cudaGetSymbolAddress((void**)&p_hw22t, g_hw22t);
    cudaGetSymbolAddress((void**)&p_hb22t, g_hb22t);

    cudaFuncSetAttribute(gemm_mma, cudaFuncAttributeMaxDynamicSharedMemorySize,
                         GEMM_SMEM);

    dim3 tb(32, 8);
    // weight transposes (+tf32 round): src [K,N] -> dst [N,K]
    transpose_k<<<dim3(H1 / 32, CIN / 32), tb>>>(l1_w, p_l1wt, CIN, H1);
    transpose_k<<<dim3(H2 / 32, H1 / 32), tb>>>(l2_w, p_l2wt, H1, H2);
    transpose_k<<<dim3(COUT / 32, H2 / 32), tb>>>(l3_w, p_l3wt, H2, COUT);
    transpose_k<<<dim3(H1 / 32, 1), tb>>>(hw1_2_w, p_hw12t, 32, H1);
    transpose_k<<<dim3(H1 / 32, 1), tb>>>(hb1_2_w, p_hb12t, 32, H1);
    transpose_k<<<dim3(H2 / 32, 1), tb>>>(hw2_2_w, p_hw22t, 32, H2);
    transpose_k<<<dim3(H2 / 32, 1), tb>>>(hb2_2_w, p_hb22t, 32, H2);

    // x_feature -> tf32-rounded copy
    {
        size_t n4 = (size_t)B * CIN / 4;
        cvt_tf32_vec<<<(unsigned)((n4 + 255) / 256), 256>>>(x_feature, p_xf, n4);
    }

    // hypernet hidden layers
    {
        int blocks = (B * 32 + 255) / 256;
        hyper_hidden<<<blocks, 256>>>(x_param, hw1_1_w, hw1_1_b, p_hw1, B);
        hyper_hidden<<<blocks, 256>>>(x_param, hb1_1_w, hb1_1_b, p_hb1, B);
        hyper_hidden<<<blocks, 256>>>(x_param, hw2_1_w, hw2_1_b, p_hw2, B);
        hyper_hidden<<<blocks, 256>>>(x_param, hb2_1_w, hb2_1_b, p_hb2, B);
    }

    const int mg = B / 128;
    // hypernet output layers -> per-sample affine params
    gemm_mma<<<dim3(H1 / 128, mg), 128, GEMM_SMEM>>>(B, H1, 32, p_hw1, p_hw12t, hw1_2_b, p_w1);
    gemm_mma<<<dim3(H1 / 128, mg), 128, GEMM_SMEM>>>(B, H1, 32, p_hb1, p_hb12t, hb1_2_b, p_b1);
    gemm_mma<<<dim3(H2 / 128, mg), 128, GEMM_SMEM>>>(B, H2, 32, p_hw2, p_hw22t, hw2_2_b, p_w2);
    gemm_mma<<<dim3(H2 / 128, mg), 128, GEMM_SMEM>>>(B, H2, 32, p_hb2, p_hb22t, hb2_2_b, p_b2);

    // base net
    gemm_mma<<<dim3(H1 / 128, mg), 128, GEMM_SMEM>>>(B, H1, CIN, p_xf, p_l1wt, l1_b, p_x1);
    gn_affine_relu<H1><<<B, 256>>>(p_x1, p_w1, p_b1);
    gemm_mma<<<dim3(H2 / 128, mg), 128, GEMM_SMEM>>>(B, H2, H1, p_x1, p_l2wt, l2_b, p_x2);
    gn_affine_relu<H2><<<B, 256>>>(p_x2, p_w2, p_b2);
    gemm_mma<<<dim3(COUT / 128, mg), 128, GEMM_SMEM>>>(B, COUT, H2, p_x2, p_l3wt, l3_b, p_x3);

    // log_softmax -> output
    logsoftmax256<<<B, 256>>>(p_x3, (float*)d_out);
}

// round 5
// speedup vs baseline: 5.5059x; 1.5412x over previous
#include <cuda_runtime.h>
#include <cuda_fp16.h>
#include <cstdint>
#include <math.h>

// ---------------------------------------------------------------------------
// Problem dims (fixed by the dataset)
// ---------------------------------------------------------------------------
#define B_MAX   32768
#define CIN     512
#define H1      2048
#define H2      1024
#define COUT    256
#define PDIM    8

// ---------------------------------------------------------------------------
// Scratch (__device__ globals: the sanctioned no-alloc workaround)
// ---------------------------------------------------------------------------
__device__ __half g_h1[B_MAX * 32];
__device__ __half g_h2[B_MAX * 32];
__device__ __half g_h3[B_MAX * 32];
__device__ __half g_h4[B_MAX * 32];
__device__ __half g_xfh[(size_t)B_MAX * CIN];
__device__ __half g_x1h[(size_t)B_MAX * H1];
__device__ __half g_x2h[(size_t)B_MAX * H2];
__device__ float  g_w1[(size_t)B_MAX * H1];
__device__ float  g_b1[(size_t)B_MAX * H1];
__device__ float  g_w2[(size_t)B_MAX * H2];
__device__ float  g_b2[(size_t)B_MAX * H2];
__device__ float  g_x1[(size_t)B_MAX * H1];
__device__ float  g_x2[(size_t)B_MAX * H2];
__device__ float  g_x3[(size_t)B_MAX * COUT];
// transposed fp16 weights [N, K]
__device__ __half g_l1wt[(size_t)H1 * CIN];
__device__ __half g_l2wt[(size_t)H2 * H1];
__device__ __half g_l3wt[(size_t)COUT * H2];
__device__ __half g_hw12t[H1 * 32];
__device__ __half g_hb12t[H1 * 32];
__device__ __half g_hw22t[H2 * 32];
__device__ __half g_hb22t[H2 * 32];

// ---------------------------------------------------------------------------
// Helpers (all architecture-portable PTX: sm_80+)
// ---------------------------------------------------------------------------
__device__ __forceinline__ uint32_t smem_u32(const void* p)
{
    uint32_t a;
    asm("{ .reg .u64 t; cvta.to.shared.u64 t, %1; cvt.u32.u64 %0, t; }"
        : "=r"(a) : "l"(p));
    return a;
}

__device__ __forceinline__ void cp_async16(uint32_t dst, const void* src)
{
    asm volatile("cp.async.cg.shared.global [%0], [%1], 16;"
                 :: "r"(dst), "l"(src));
}
__device__ __forceinline__ void cp_commit()
{
    asm volatile("cp.async.commit_group;" ::: "memory");
}
template <int N>
__device__ __forceinline__ void cp_wait()
{
    asm volatile("cp.async.wait_group %0;" :: "n"(N) : "memory");
}

// fp16 m16n8k16 mma, fp32 accumulate (portable since sm_80)
__device__ __forceinline__ void mma16(float* d, const uint32_t* a, const uint32_t* b)
{
    asm volatile(
        "mma.sync.aligned.m16n8k16.row.col.f32.f16.f16.f32 "
        "{%0,%1,%2,%3}, {%4,%5,%6,%7}, {%8,%9}, {%0,%1,%2,%3};"
        : "+f"(d[0]), "+f"(d[1]), "+f"(d[2]), "+f"(d[3])
        : "r"(a[0]), "r"(a[1]), "r"(a[2]), "r"(a[3]), "r"(b[0]), "r"(b[1]));
}

__device__ __forceinline__ void ldsm4(uint32_t* r, uint32_t addr)
{
    asm volatile("ldmatrix.sync.aligned.m8n8.x4.shared.b16 {%0,%1,%2,%3}, [%4];"
                 : "=r"(r[0]), "=r"(r[1]), "=r"(r[2]), "=r"(r[3]) : "r"(addr));
}

// ---------------------------------------------------------------------------
// fp16 tensor-core GEMM:  C[M,N] = A[M,K] @ Bt[N,K]^T + bias[N]   (fp32 out)
// BM=BN=128, BK=BKH halves; 128 threads = 4 warps (2x2), 64x64 per warp.
// M%128==0, N%128==0, K%BKH==0.
// ---------------------------------------------------------------------------
template <int BKH>
__global__ __launch_bounds__(128, 2) void gemm_h(
    int M, int N, int K,
    const __half* __restrict__ A, const __half* __restrict__ Bt,
    const float* __restrict__ bias, float* __restrict__ C)
{
    constexpr int LDH = BKH + 8;            // padded row stride (halves)
    constexpr int TILE_H = 128 * LDH;       // halves per tile per stage
    constexpr int CPR = BKH / 8;            // 16B chunks per row
    constexpr int KS = BKH / 16;            // k16 steps per tile

    extern __shared__ __half smh[];
    __half* As = smh;                        // [2][128][LDH]
    __half* Bs = smh + 2 * TILE_H;

    const int tid = threadIdx.x;
    const int lane = tid & 31, wid = tid >> 5;
    const int wm = wid & 1, wn = wid >> 1;
    const int m0 = blockIdx.y * 128;
    const int n0 = blockIdx.x * 128;
    const int nkt = K / BKH;

    const __half* Ag = A + (size_t)m0 * K;
    const __half* Bg = Bt + (size_t)n0 * K;
    const uint32_t sA = smem_u32(As);
    const uint32_t sB = smem_u32(Bs);

    // ldmatrix per-thread byte offsets within a tile
    // A: lanes 0-15 -> rows 0-15 @k0 ; lanes 16-31 -> rows 0-15 @k8 (+16B)
    const uint32_t a_off =
        (uint32_t)(((wm * 64 + (lane & 15)) * LDH + ((lane >> 4) << 3)) * 2);
    // B: lanes 0-7 n0-7@k0 ; 8-15 n0-7@k8 ; 16-23 n8-15@k0 ; 24-31 n8-15@k8
    const uint32_t b_off =
        (uint32_t)(((wn * 64 + ((lane >> 4) << 3) + (lane & 7)) * LDH +
                    (((lane >> 3) & 1) << 3)) * 2);

    float acc[4][8][4];
#pragma unroll
    for (int mt = 0; mt < 4; mt++)
#pragma unroll
        for (int nt = 0; nt < 8; nt++)
#pragma unroll
            for (int j = 0; j < 4; j++) acc[mt][nt][j] = 0.0f;

    auto load_tiles = [&](int t) {
        const int s = t & 1;
        const uint32_t da = sA + s * (TILE_H * 2);
        const uint32_t db = sB + s * (TILE_H * 2);
        const __half* ga = Ag + t * BKH;
        const __half* gb = Bg + t * BKH;
#pragma unroll
        for (int it = 0; it < CPR; it++) {
            int idx = tid + it * 128;
            int r = idx / CPR, cc = idx % CPR;
            uint32_t off = r * (LDH * 2) + cc * 16;
            cp_async16(da + off, ga + (size_t)r * K + cc * 8);
            cp_async16(db + off, gb + (size_t)r * K + cc * 8);
        }
    };

    load_tiles(0);
    cp_commit();

    for (int i = 0; i < nkt; i++) {
        if (i + 1 < nkt) {
            load_tiles(i + 1);
            cp_commit();
            cp_wait<1>();
        } else {
            cp_wait<0>();
        }
        __syncthreads();

        const int s = i & 1;
        const uint32_t sa = sA + s * (TILE_H * 2) + a_off;
        const uint32_t sb = sB + s * (TILE_H * 2) + b_off;

#pragma unroll
        for (int ks = 0; ks < KS; ks++) {
            uint32_t af[4][4], bf[4][4];
#pragma unroll
            for (int mt = 0; mt < 4; mt++)
                ldsm4(af[mt], sa + (uint32_t)((mt * 16 * LDH + ks * 16) * 2));
#pragma unroll
            for (int np = 0; np < 4; np++)
                ldsm4(bf[np], sb + (uint32_t)((np * 16 * LDH + ks * 16) * 2));
#pragma unroll
            for (int mt = 0; mt < 4; mt++)
#pragma unroll
                for (int nt = 0; nt < 8; nt++)
                    mma16(acc[mt][nt], af[mt], bf[nt >> 1] + (nt & 1) * 2);
        }
        __syncthreads();
    }

    // ---- epilogue: bias + fp32 store ----
    const int arow = lane >> 2;
    const int acol = lane & 3;
    float2 bv[8];
#pragma unroll
    for (int nt = 0; nt < 8; nt++) {
        int cc = n0 + wn * 64 + nt * 8 + acol * 2;
        bv[nt] = *(const float2*)&bias[cc];
    }
#pragma unroll
    for (int mt = 0; mt < 4; mt++) {
        size_t r0 = (size_t)m0 + wm * 64 + mt * 16 + arow;
#pragma unroll
        for (int nt = 0; nt < 8; nt++) {
            int cc = n0 + wn * 64 + nt * 8 + acol * 2;
            float2 v0 = { acc[mt][nt][0] + bv[nt].x, acc[mt][nt][1] + bv[nt].y };
            float2 v1 = { acc[mt][nt][2] + bv[nt].x, acc[mt][nt][3] + bv[nt].y };
            *(float2*)&C[r0 * N + cc] = v0;
            *(float2*)&C[(r0 + 8) * N + cc] = v1;
        }
    }
}

// ---------------------------------------------------------------------------
// Weight transpose + fp16 convert: src fp32 [K, N] -> dst fp16 [N, K]
// ---------------------------------------------------------------------------
__global__ void transpose_k(const float* __restrict__ src, __half* __restrict__ dst,
                            int K, int N)
{
    __shared__ float t[32][33];
    int x = blockIdx.x * 32 + threadIdx.x;
    int y0 = blockIdx.y * 32;
#pragma unroll
    for (int j = 0; j < 32; j += 8)
        t[threadIdx.y + j][threadIdx.x] = src[(size_t)(y0 + threadIdx.y + j) * N + x];
    __syncthreads();
    int x2 = y0 + threadIdx.x;
    int y2 = blockIdx.x * 32 + threadIdx.y;
#pragma unroll
    for (int j = 0; j < 32; j += 8)
        dst[(size_t)(y2 + j) * K + x2] = __float2half_rn(t[threadIdx.x][threadIdx.y + j]);
}

// ---------------------------------------------------------------------------
// Elementwise fp32 -> fp16 (x_feature)
// ---------------------------------------------------------------------------
__global__ __launch_bounds__(256) void cvt_h_vec(
    const float* __restrict__ in, __half* __restrict__ out, size_t n4)
{
    size_t i = (size_t)blockIdx.x * blockDim.x + threadIdx.x;
    if (i >= n4) return;
    float4 v = ((const float4*)in)[i];
    __half2 a = __floats2half2_rn(v.x, v.y);
    __half2 b = __floats2half2_rn(v.z, v.w);
    ((__half2*)out)[i * 2] = a;
    ((__half2*)out)[i * 2 + 1] = b;
}

// ---------------------------------------------------------------------------
// Hypernet hidden: H = fp16(relu(P @ W + b)), P:[B,8], W:[8,32]
// ---------------------------------------------------------------------------
__global__ __launch_bounds__(256) void hyper_hidden(
    const float* __restrict__ P, const float* __restrict__ W,
    const float* __restrict__ bias, __half* __restrict__ H, int B)
{
    int idx = blockIdx.x * blockDim.x + threadIdx.x;
    int row = idx >> 5;
    int j = idx & 31;
    if (row >= B) return;
    float s = bias[j];
#pragma unroll
    for (int k = 0; k < PDIM; k++)
        s += P[row * PDIM + k] * W[k * 32 + j];
    H[(size_t)row * 32 + j] = __float2half_rn(fmaxf(s, 0.0f));
}

// ---------------------------------------------------------------------------
// Per-sample groupnorm (n_group=1) + per-sample affine + ReLU -> fp16 out.
// One row per block, 256 threads.
// ---------------------------------------------------------------------------
__device__ __forceinline__ float warpReduceSum(float v)
{
#pragma unroll
    for (int o = 16; o > 0; o >>= 1) v += __shfl_xor_sync(0xffffffffu, v, o);
    return v;
}

template <int C>
__global__ __launch_bounds__(256) void gn_affine_relu(
    const float* __restrict__ x, const float* __restrict__ w,
    const float* __restrict__ b, __half* __restrict__ out)
{
    constexpr int PER = C / 256;
    const int row = blockIdx.x;
    const int tid = threadIdx.x;
    const size_t base = (size_t)row * C;

    float v[PER];
    float s = 0.0f, s2 = 0.0f;
#pragma unroll
    for (int i = 0; i < PER; i++) {
        float t = x[base + tid + i * 256];
        v[i] = t;
        s += t;
        s2 += t * t;
    }

    __shared__ float sh[16];
    s = warpReduceSum(s);
    s2 = warpReduceSum(s2);
    int lane = tid & 31, wid = tid >> 5;
    if (lane == 0) { sh[wid] = s; sh[8 + wid] = s2; }
    __syncthreads();
    if (tid < 32) {
        float a = (lane < 8) ? sh[lane] : 0.0f;
        float c = (lane < 8) ? sh[8 + lane] : 0.0f;
        a = warpReduceSum(a);
        c = warpReduceSum(c);
        if (lane == 0) { sh[0] = a; sh[1] = c; }
    }
    __syncthreads();

    const float invC = 1.0f / (float)C;
    float mean = sh[0] * invC;
    float var = sh[1] * invC - mean * mean;
    float inv = rsqrtf(var + 1e-5f);

#pragma unroll
    for (int i = 0; i < PER; i++) {
        int c = tid + i * 256;
        float y = (v[i] - mean) * inv * w[base + c] + b[base + c];
        out[base + c] = __float2half_rn(fmaxf(y, 0.0f));
    }
}

// ---------------------------------------------------------------------------
// log_softmax over 256 columns, one row per block (256 threads).
// ---------------------------------------------------------------------------
__global__ __launch_bounds__(256) void logsoftmax256(
    const float* __restrict__ x, float* __restrict__ out)
{
    const int row = blockIdx.x;
    const int tid = threadIdx.x;
    const size_t base = (size_t)row * 256;
    float v = x[base + tid];

    __shared__ float shm[8];
    __shared__ float shs[8];

    float m = v;
#pragma unroll
    for (int o = 16; o > 0; o >>= 1) m = fmaxf(m, __shfl_xor_sync(0xffffffffu, m, o));
    if ((tid & 31) == 0) shm[tid >> 5] = m;
    __syncthreads();
    float mx = shm[0];
#pragma unroll
    for (int i = 1; i < 8; i++) mx = fmaxf(mx, shm[i]);

    float e = expf(v - mx);
    float se = warpReduceSum(e);
    if ((tid & 31) == 0) shs[tid >> 5] = se;
    __syncthreads();
    float tot = 0.0f;
#pragma unroll
    for (int i = 0; i < 8; i++) tot += shs[i];

    out[base + tid] = (v - mx) - logf(tot);
}

// ---------------------------------------------------------------------------
// kernel_launch
// ---------------------------------------------------------------------------
extern "C" void kernel_launch(void* const* d_in, const int* in_sizes, int n_in,
                              void* d_out, int out_size)
{
    const float* x_feature = (const float*)d_in[0];
    const float* x_param   = (const float*)d_in[1];
    const float* hw1_1_w   = (const float*)d_in[2];
    const float* hw1_1_b   = (const float*)d_in[3];
    const float* hw1_2_w   = (const float*)d_in[4];
    const float* hw1_2_b   = (const float*)d_in[5];
    const float* hb1_1_w   = (const float*)d_in[6];
    const float* hb1_1_b   = (const float*)d_in[7];
    const float* hb1_2_w   = (const float*)d_in[8];
    const float* hb1_2_b   = (const float*)d_in[9];
    const float* hw2_1_w   = (const float*)d_in[10];
    const float* hw2_1_b   = (const float*)d_in[11];
    const float* hw2_2_w   = (const float*)d_in[12];
    const float* hw2_2_b   = (const float*)d_in[13];
    const float* hb2_1_w   = (const float*)d_in[14];
    const float* hb2_1_b   = (const float*)d_in[15];
    const float* hb2_2_w   = (const float*)d_in[16];
    const float* hb2_2_b   = (const float*)d_in[17];
    const float* l1_w      = (const float*)d_in[18];
    const float* l1_b      = (const float*)d_in[19];
    const float* l2_w      = (const float*)d_in[20];
    const float* l2_b      = (const float*)d_in[21];
    const float* l3_w      = (const float*)d_in[22];
    const float* l3_b      = (const float*)d_in[23];

    const int B = in_sizes[0] / CIN;   // 32768

    __half *p_h1, *p_h2, *p_h3, *p_h4, *p_xfh, *p_x1h, *p_x2h;
    __half *p_l1wt, *p_l2wt, *p_l3wt, *p_hw12t, *p_hb12t, *p_hw22t, *p_hb22t;
    float *p_w1, *p_b1, *p_w2, *p_b2, *p_x1, *p_x2, *p_x3;
    cudaGetSymbolAddress((void**)&p_h1, g_h1);
    cudaGetSymbolAddress((void**)&p_h2, g_h2);
    cudaGetSymbolAddress((void**)&p_h3, g_h3);
    cudaGetSymbolAddress((void**)&p_h4, g_h4);
    cudaGetSymbolAddress((void**)&p_xfh, g_xfh);
    cudaGetSymbolAddress((void**)&p_x1h, g_x1h);
    cudaGetSymbolAddress((void**)&p_x2h, g_x2h);
    cudaGetSymbolAddress((void**)&p_w1, g_w1);
    cudaGetSymbolAddress((void**)&p_b1, g_b1);
    cudaGetSymbolAddress((void**)&p_w2, g_w2);
    cudaGetSymbolAddress((void**)&p_b2, g_b2);
    cudaGetSymbolAddress((void**)&p_x1, g_x1);
    cudaGetSymbolAddress((void**)&p_x2, g_x2);
    cudaGetSymbolAddress((void**)&p_x3, g_x3);
    cudaGetSymbolAddress((void**)&p_l1wt, g_l1wt);
    cudaGetSymbolAddress((void**)&p_l2wt, g_l2wt);
    cudaGetSymbolAddress((void**)&p_l3wt, g_l3wt);
    cudaGetSymbolAddress((void**)&p_hw12t, g_hw12t);
    cudaGetSymbolAddress((void**)&p_hb12t, g_hb12t);
    cudaGetSymbolAddress((void**)&p_hw22t, g_hw22t);
    cudaGetSymbolAddress((void**)&p_hb22t, g_hb22t);

    constexpr int SMEM64 = 2 * 2 * 128 * (64 + 8) * 2;  // 73728
    constexpr int SMEM32 = 2 * 2 * 128 * (32 + 8) * 2;  // 40960
    cudaFuncSetAttribute(gemm_h<64>, cudaFuncAttributeMaxDynamicSharedMemorySize, SMEM64);
    cudaFuncSetAttribute(gemm_h<32>, cudaFuncAttributeMaxDynamicSharedMemorySize, SMEM32);

    dim3 tb(32, 8);
    // weight transposes (+fp16 convert): src [K,N] -> dst [N,K]
    transpose_k<<<dim3(H1 / 32, CIN / 32), tb>>>(l1_w, p_l1wt, CIN, H1);
    transpose_k<<<dim3(H2 / 32, H1 / 32), tb>>>(l2_w, p_l2wt, H1, H2);
    transpose_k<<<dim3(COUT / 32, H2 / 32), tb>>>(l3_w, p_l3wt, H2, COUT);
    transpose_k<<<dim3(H1 / 32, 1), tb>>>(hw1_2_w, p_hw12t, 32, H1);
    transpose_k<<<dim3(H1 / 32, 1), tb>>>(hb1_2_w, p_hb12t, 32, H1);
    transpose_k<<<dim3(H2 / 32, 1), tb>>>(hw2_2_w, p_hw22t, 32, H2);
    transpose_k<<<dim3(H2 / 32, 1), tb>>>(hb2_2_w, p_hb22t, 32, H2);

    // x_feature -> fp16
    {
        size_t n4 = (size_t)B * CIN / 4;
        cvt_h_vec<<<(unsigned)((n4 + 255) / 256), 256>>>(x_feature, p_xfh, n4);
    }

    // hypernet hidden layers
    {
        int blocks = (B * 32 + 255) / 256;
        hyper_hidden<<<blocks, 256>>>(x_param, hw1_1_w, hw1_1_b, p_h1, B);
        hyper_hidden<<<blocks, 256>>>(x_param, hb1_1_w, hb1_1_b, p_h2, B);
        hyper_hidden<<<blocks, 256>>>(x_param, hw2_1_w, hw2_1_b, p_h3, B);
        hyper_hidden<<<blocks, 256>>>(x_param, hb2_1_w, hb2_1_b, p_h4, B);
    }

    const int mg = B / 128;
    // hypernet output layers -> per-sample affine params (fp32)
    gemm_h<32><<<dim3(H1 / 128, mg), 128, SMEM32>>>(B, H1, 32, p_h1, p_hw12t, hw1_2_b, p_w1);
    gemm_h<32><<<dim3(H1 / 128, mg), 128, SMEM32>>>(B, H1, 32, p_h2, p_hb12t, hb1_2_b, p_b1);
    gemm_h<32><<<dim3(H2 / 128, mg), 128, SMEM32>>>(B, H2, 32, p_h3, p_hw22t, hw2_2_b, p_w2);
    gemm_h<32><<<dim3(H2 / 128, mg), 128, SMEM32>>>(B, H2, 32, p_h4, p_hb22t, hb2_2_b, p_b2);

    // base net
    gemm_h<64><<<dim3(H1 / 128, mg), 128, SMEM64>>>(B, H1, CIN, p_xfh, p_l1wt, l1_b, p_x1);
    gn_affine_relu<H1><<<B, 256>>>(p_x1, p_w1, p_b1, p_x1h);
    gemm_h<64><<<dim3(H2 / 128, mg), 128, SMEM64>>>(B, H2, H1, p_x1h, p_l2wt, l2_b, p_x2);
    gn_affine_relu<H2><<<B, 256>>>(p_x2, p_w2, p_b2, p_x2h);
    gemm_h<64><<<dim3(COUT / 128, mg), 128, SMEM64>>>(B, COUT, H2, p_x2h, p_l3wt, l3_b, p_x3);

    // log_softmax -> output
    logsoftmax256<<<B, 256>>>(p_x3, (float*)d_out);
}

// round 6
// speedup vs baseline: 5.9466x; 1.0800x over previous
#include <cuda_runtime.h>
#include <cuda_fp16.h>
#include <cstdint>
#include <math.h>

// ---------------------------------------------------------------------------
// Problem dims (fixed by the dataset)
// ---------------------------------------------------------------------------
#define B_MAX   32768
#define CIN     512
#define H1      2048
#define H2      1024
#define COUT    256
#define PDIM    8

// ---------------------------------------------------------------------------
// Scratch (__device__ globals: the sanctioned no-alloc workaround)
// ---------------------------------------------------------------------------
__device__ __half g_h1[B_MAX * 32];
__device__ __half g_h2[B_MAX * 32];
__device__ __half g_h3[B_MAX * 32];
__device__ __half g_h4[B_MAX * 32];
__device__ __half g_xfh[(size_t)B_MAX * CIN];
__device__ __half g_x1h[(size_t)B_MAX * H1];
__device__ __half g_x2h[(size_t)B_MAX * H2];
__device__ __half g_w1h[(size_t)B_MAX * H1];
__device__ __half g_b1h[(size_t)B_MAX * H1];
__device__ __half g_w2h[(size_t)B_MAX * H2];
__device__ __half g_b2h[(size_t)B_MAX * H2];
__device__ float  g_x3[(size_t)B_MAX * COUT];
// transposed fp16 weights [N, K]
__device__ __half g_l1wt[(size_t)H1 * CIN];
__device__ __half g_l2wt[(size_t)H2 * H1];
__device__ __half g_l3wt[(size_t)COUT * H2];
__device__ __half g_hw12t[H1 * 32];
__device__ __half g_hb12t[H1 * 32];
__device__ __half g_hw22t[H2 * 32];
__device__ __half g_hb22t[H2 * 32];

// ---------------------------------------------------------------------------
// Helpers (all architecture-portable PTX: sm_80+)
// ---------------------------------------------------------------------------
__device__ __forceinline__ uint32_t smem_u32(const void* p)
{
    uint32_t a;
    asm("{ .reg .u64 t; cvta.to.shared.u64 t, %1; cvt.u32.u64 %0, t; }"
        : "=r"(a) : "l"(p));
    return a;
}

__device__ __forceinline__ void cp_async16(uint32_t dst, const void* src)
{
    asm volatile("cp.async.cg.shared.global [%0], [%1], 16;"
                 :: "r"(dst), "l"(src));
}
__device__ __forceinline__ void cp_commit()
{
    asm volatile("cp.async.commit_group;" ::: "memory");
}
template <int N>
__device__ __forceinline__ void cp_wait()
{
    asm volatile("cp.async.wait_group %0;" :: "n"(N) : "memory");
}

// fp16 m16n8k16 mma, fp32 accumulate (portable since sm_80)
__device__ __forceinline__ void mma16(float* d, const uint32_t* a, const uint32_t* b)
{
    asm volatile(
        "mma.sync.aligned.m16n8k16.row.col.f32.f16.f16.f32 "
        "{%0,%1,%2,%3}, {%4,%5,%6,%7}, {%8,%9}, {%0,%1,%2,%3};"
        : "+f"(d[0]), "+f"(d[1]), "+f"(d[2]), "+f"(d[3])
        : "r"(a[0]), "r"(a[1]), "r"(a[2]), "r"(a[3]), "r"(b[0]), "r"(b[1]));
}

__device__ __forceinline__ void ldsm4(uint32_t* r, uint32_t addr)
{
    asm volatile("ldmatrix.sync.aligned.m8n8.x4.shared.b16 {%0,%1,%2,%3}, [%4];"
                 : "=r"(r[0]), "=r"(r[1]), "=r"(r[2]), "=r"(r[3]) : "r"(addr));
}

// ---------------------------------------------------------------------------
// fp16 tensor-core GEMM:  C[M,N] = A[M,K] @ Bt[N,K]^T + bias[N]
// BM=BN=128, BK=BKH halves; 128 threads = 4 warps (2x2), 64x64 per warp.
// Output type OutT = float or __half.  M%128==0, N%128==0, K%BKH==0.
// ---------------------------------------------------------------------------
template <int BKH, typename OutT>
__global__ __launch_bounds__(128, 2) void gemm_h(
    int M, int N, int K,
    const __half* __restrict__ A, const __half* __restrict__ Bt,
    const float* __restrict__ bias, OutT* __restrict__ C)
{
    constexpr int LDH = BKH + 8;            // padded row stride (halves)
    constexpr int TILE_H = 128 * LDH;       // halves per tile per stage
    constexpr int CPR = BKH / 8;            // 16B chunks per row
    constexpr int KS = BKH / 16;            // k16 steps per tile

    extern __shared__ __half smh[];
    __half* As = smh;                        // [2][128][LDH]
    __half* Bs = smh + 2 * TILE_H;

    const int tid = threadIdx.x;
    const int lane = tid & 31, wid = tid >> 5;
    const int wm = wid & 1, wn = wid >> 1;
    const int m0 = blockIdx.y * 128;
    const int n0 = blockIdx.x * 128;
    const int nkt = K / BKH;

    const __half* Ag = A + (size_t)m0 * K;
    const __half* Bg = Bt + (size_t)n0 * K;
    const uint32_t sA = smem_u32(As);
    const uint32_t sB = smem_u32(Bs);

    const uint32_t a_off =
        (uint32_t)(((wm * 64 + (lane & 15)) * LDH + ((lane >> 4) << 3)) * 2);
    const uint32_t b_off =
        (uint32_t)(((wn * 64 + ((lane >> 4) << 3) + (lane & 7)) * LDH +
                    (((lane >> 3) & 1) << 3)) * 2);

    float acc[4][8][4];
#pragma unroll
    for (int mt = 0; mt < 4; mt++)
#pragma unroll
        for (int nt = 0; nt < 8; nt++)
#pragma unroll
            for (int j = 0; j < 4; j++) acc[mt][nt][j] = 0.0f;

    auto load_tiles = [&](int t) {
        const int s = t & 1;
        const uint32_t da = sA + s * (TILE_H * 2);
        const uint32_t db = sB + s * (TILE_H * 2);
        const __half* ga = Ag + t * BKH;
        const __half* gb = Bg + t * BKH;
#pragma unroll
        for (int it = 0; it < CPR; it++) {
            int idx = tid + it * 128;
            int r = idx / CPR, cc = idx % CPR;
            uint32_t off = r * (LDH * 2) + cc * 16;
            cp_async16(da + off, ga + (size_t)r * K + cc * 8);
            cp_async16(db + off, gb + (size_t)r * K + cc * 8);
        }
    };

    load_tiles(0);
    cp_commit();

    for (int i = 0; i < nkt; i++) {
        if (i + 1 < nkt) {
            load_tiles(i + 1);
            cp_commit();
            cp_wait<1>();
        } else {
            cp_wait<0>();
        }
        __syncthreads();

        const int s = i & 1;
        const uint32_t sa = sA + s * (TILE_H * 2) + a_off;
        const uint32_t sb = sB + s * (TILE_H * 2) + b_off;

#pragma unroll
        for (int ks = 0; ks < KS; ks++) {
            uint32_t af[4][4], bf[4][4];
#pragma unroll
            for (int mt = 0; mt < 4; mt++)
                ldsm4(af[mt], sa + (uint32_t)((mt * 16 * LDH + ks * 16) * 2));
#pragma unroll
            for (int np = 0; np < 4; np++)
                ldsm4(bf[np], sb + (uint32_t)((np * 16 * LDH + ks * 16) * 2));
#pragma unroll
            for (int mt = 0; mt < 4; mt++)
#pragma unroll
                for (int nt = 0; nt < 8; nt++)
                    mma16(acc[mt][nt], af[mt], bf[nt >> 1] + (nt & 1) * 2);
        }
        __syncthreads();
    }

    // ---- epilogue: bias + store (fp32 or fp16) ----
    const int arow = lane >> 2;
    const int acol = lane & 3;
    float2 bv[8];
#pragma unroll
    for (int nt = 0; nt < 8; nt++) {
        int cc = n0 + wn * 64 + nt * 8 + acol * 2;
        bv[nt] = *(const float2*)&bias[cc];
    }
#pragma unroll
    for (int mt = 0; mt < 4; mt++) {
        size_t r0 = (size_t)m0 + wm * 64 + mt * 16 + arow;
#pragma unroll
        for (int nt = 0; nt < 8; nt++) {
            int cc = n0 + wn * 64 + nt * 8 + acol * 2;
            float v00 = acc[mt][nt][0] + bv[nt].x;
            float v01 = acc[mt][nt][1] + bv[nt].y;
            float v10 = acc[mt][nt][2] + bv[nt].x;
            float v11 = acc[mt][nt][3] + bv[nt].y;
            if constexpr (sizeof(OutT) == 2) {
                *(__half2*)&C[r0 * N + cc] = __floats2half2_rn(v00, v01);
                *(__half2*)&C[(r0 + 8) * N + cc] = __floats2half2_rn(v10, v11);
            } else {
                float2 a0 = { v00, v01 }, a1 = { v10, v11 };
                *(float2*)&C[r0 * N + cc] = a0;
                *(float2*)&C[(r0 + 8) * N + cc] = a1;
            }
        }
    }
}

// ---------------------------------------------------------------------------
// Weight transpose + fp16 convert: src fp32 [K, N] -> dst fp16 [N, K]
// ---------------------------------------------------------------------------
__global__ void transpose_k(const float* __restrict__ src, __half* __restrict__ dst,
                            int K, int N)
{
    __shared__ float t[32][33];
    int x = blockIdx.x * 32 + threadIdx.x;
    int y0 = blockIdx.y * 32;
#pragma unroll
    for (int j = 0; j < 32; j += 8)
        t[threadIdx.y + j][threadIdx.x] = src[(size_t)(y0 + threadIdx.y + j) * N + x];
    __syncthreads();
    int x2 = y0 + threadIdx.x;
    int y2 = blockIdx.x * 32 + threadIdx.y;
#pragma unroll
    for (int j = 0; j < 32; j += 8)
        dst[(size_t)(y2 + j) * K + x2] = __float2half_rn(t[threadIdx.x][threadIdx.y + j]);
}

// ---------------------------------------------------------------------------
// Elementwise fp32 -> fp16 (x_feature)
// ---------------------------------------------------------------------------
__global__ __launch_bounds__(256) void cvt_h_vec(
    const float* __restrict__ in, __half* __restrict__ out, size_t n4)
{
    size_t i = (size_t)blockIdx.x * blockDim.x + threadIdx.x;
    if (i >= n4) return;
    float4 v = ((const float4*)in)[i];
    ((__half2*)out)[i * 2] = __floats2half2_rn(v.x, v.y);
    ((__half2*)out)[i * 2 + 1] = __floats2half2_rn(v.z, v.w);
}

// ---------------------------------------------------------------------------
// Hypernet hidden: H = fp16(relu(P @ W + b)), P:[B,8], W:[8,32]
// ---------------------------------------------------------------------------
__global__ __launch_bounds__(256) void hyper_hidden(
    const float* __restrict__ P, const float* __restrict__ W,
    const float* __restrict__ bias, __half* __restrict__ H, int B)
{
    int idx = blockIdx.x * blockDim.x + threadIdx.x;
    int row = idx >> 5;
    int j = idx & 31;
    if (row >= B) return;
    float s = bias[j];
#pragma unroll
    for (int k = 0; k < PDIM; k++)
        s += P[row * PDIM + k] * W[k * 32 + j];
    H[(size_t)row * 32 + j] = __float2half_rn(fmaxf(s, 0.0f));
}

// ---------------------------------------------------------------------------
// Per-sample groupnorm (n_group=1) + per-sample fp16 affine + ReLU, fp16
// in/out, in place. One row per block, 256 threads. fp32 statistics.
// ---------------------------------------------------------------------------
__device__ __forceinline__ float warpReduceSum(float v)
{
#pragma unroll
    for (int o = 16; o > 0; o >>= 1) v += __shfl_xor_sync(0xffffffffu, v, o);
    return v;
}

template <int C>
__global__ __launch_bounds__(256) void gn_affine_relu(
    __half* x, const __half* __restrict__ w, const __half* __restrict__ b)
{
    constexpr int PER2 = C / 512;          // half2 per thread
    const int row = blockIdx.x;
    const int tid = threadIdx.x;
    __half2* xr = (__half2*)(x + (size_t)row * C);
    const __half2* wr = (const __half2*)(w + (size_t)row * C);
    const __half2* br = (const __half2*)(b + (size_t)row * C);

    float2 v[PER2];
    float s = 0.0f, s2 = 0.0f;
#pragma unroll
    for (int i = 0; i < PER2; i++) {
        float2 t = __half22float2(xr[tid + i * 256]);
        v[i] = t;
        s += t.x + t.y;
        s2 += t.x * t.x + t.y * t.y;
    }

    __shared__ float sh[16];
    s = warpReduceSum(s);
    s2 = warpReduceSum(s2);
    int lane = tid & 31, wid = tid >> 5;
    if (lane == 0) { sh[wid] = s; sh[8 + wid] = s2; }
    __syncthreads();
    if (tid < 32) {
        float a = (lane < 8) ? sh[lane] : 0.0f;
        float c = (lane < 8) ? sh[8 + lane] : 0.0f;
        a = warpReduceSum(a);
        c = warpReduceSum(c);
        if (lane == 0) { sh[0] = a; sh[1] = c; }
    }
    __syncthreads();

    const float invC = 1.0f / (float)C;
    float mean = sh[0] * invC;
    float var = sh[1] * invC - mean * mean;
    float inv = rsqrtf(var + 1e-5f);

#pragma unroll
    for (int i = 0; i < PER2; i++) {
        float2 wv = __half22float2(wr[tid + i * 256]);
        float2 bb = __half22float2(br[tid + i * 256]);
        float y0 = (v[i].x - mean) * inv * wv.x + bb.x;
        float y1 = (v[i].y - mean) * inv * wv.y + bb.y;
        xr[tid + i * 256] = __floats2half2_rn(fmaxf(y0, 0.0f), fmaxf(y1, 0.0f));
    }
}

// ---------------------------------------------------------------------------
// log_softmax over 256 columns, one row per block (256 threads).
// ---------------------------------------------------------------------------
__global__ __launch_bounds__(256) void logsoftmax256(
    const float* __restrict__ x, float* __restrict__ out)
{
    const int row = blockIdx.x;
    const int tid = threadIdx.x;
    const size_t base = (size_t)row * 256;
    float v = x[base + tid];

    __shared__ float shm[8];
    __shared__ float shs[8];

    float m = v;
#pragma unroll
    for (int o = 16; o > 0; o >>= 1) m = fmaxf(m, __shfl_xor_sync(0xffffffffu, m, o));
    if ((tid & 31) == 0) shm[tid >> 5] = m;
    __syncthreads();
    float mx = shm[0];
#pragma unroll
    for (int i = 1; i < 8; i++) mx = fmaxf(mx, shm[i]);

    float e = expf(v - mx);
    float se = warpReduceSum(e);
    if ((tid & 31) == 0) shs[tid >> 5] = se;
    __syncthreads();
    float tot = 0.0f;
#pragma unroll
    for (int i = 0; i < 8; i++) tot += shs[i];

    out[base + tid] = (v - mx) - logf(tot);
}

// ---------------------------------------------------------------------------
// kernel_launch
// ---------------------------------------------------------------------------
extern "C" void kernel_launch(void* const* d_in, const int* in_sizes, int n_in,
                              void* d_out, int out_size)
{
    const float* x_feature = (const float*)d_in[0];
    const float* x_param   = (const float*)d_in[1];
    const float* hw1_1_w   = (const float*)d_in[2];
    const float* hw1_1_b   = (const float*)d_in[3];
    const float* hw1_2_w   = (const float*)d_in[4];
    const float* hw1_2_b   = (const float*)d_in[5];
    const float* hb1_1_w   = (const float*)d_in[6];
    const float* hb1_1_b   = (const float*)d_in[7];
    const float* hb1_2_w   = (const float*)d_in[8];
    const float* hb1_2_b   = (const float*)d_in[9];
    const float* hw2_1_w   = (const float*)d_in[10];
    const float* hw2_1_b   = (const float*)d_in[11];
    const float* hw2_2_w   = (const float*)d_in[12];
    const float* hw2_2_b   = (const float*)d_in[13];
    const float* hb2_1_w   = (const float*)d_in[14];
    const float* hb2_1_b   = (const float*)d_in[15];
    const float* hb2_2_w   = (const float*)d_in[16];
    const float* hb2_2_b   = (const float*)d_in[17];
    const float* l1_w      = (const float*)d_in[18];
    const float* l1_b      = (const float*)d_in[19];
    const float* l2_w      = (const float*)d_in[20];
    const float* l2_b      = (const float*)d_in[21];
    const float* l3_w      = (const float*)d_in[22];
    const float* l3_b      = (const float*)d_in[23];

    const int B = in_sizes[0] / CIN;   // 32768

    __half *p_h1, *p_h2, *p_h3, *p_h4, *p_xfh, *p_x1h, *p_x2h;
    __half *p_w1h, *p_b1h, *p_w2h, *p_b2h;
    __half *p_l1wt, *p_l2wt, *p_l3wt, *p_hw12t, *p_hb12t, *p_hw22t, *p_hb22t;
    float *p_x3;
    cudaGetSymbolAddress((void**)&p_h1, g_h1);
    cudaGetSymbolAddress((void**)&p_h2, g_h2);
    cudaGetSymbolAddress((void**)&p_h3, g_h3);
    cudaGetSymbolAddress((void**)&p_h4, g_h4);
    cudaGetSymbolAddress((void**)&p_xfh, g_xfh);
    cudaGetSymbolAddress((void**)&p_x1h, g_x1h);
    cudaGetSymbolAddress((void**)&p_x2h, g_x2h);
    cudaGetSymbolAddress((void**)&p_w1h, g_w1h);
    cudaGetSymbolAddress((void**)&p_b1h, g_b1h);
    cudaGetSymbolAddress((void**)&p_w2h, g_w2h);
    cudaGetSymbolAddress((void**)&p_b2h, g_b2h);
    cudaGetSymbolAddress((void**)&p_x3, g_x3);
    cudaGetSymbolAddress((void**)&p_l1wt, g_l1wt);
    cudaGetSymbolAddress((void**)&p_l2wt, g_l2wt);
    cudaGetSymbolAddress((void**)&p_l3wt, g_l3wt);
    cudaGetSymbolAddress((void**)&p_hw12t, g_hw12t);
    cudaGetSymbolAddress((void**)&p_hb12t, g_hb12t);
    cudaGetSymbolAddress((void**)&p_hw22t, g_hw22t);
    cudaGetSymbolAddress((void**)&p_hb22t, g_hb22t);

    constexpr int SMEM64 = 2 * 2 * 128 * (64 + 8) * 2;  // 73728
    constexpr int SMEM32 = 2 * 2 * 128 * (32 + 8) * 2;  // 40960
    cudaFuncSetAttribute((const void*)gemm_h<64, __half>, cudaFuncAttributeMaxDynamicSharedMemorySize, SMEM64);
    cudaFuncSetAttribute((const void*)gemm_h<64, float>,  cudaFuncAttributeMaxDynamicSharedMemorySize, SMEM64);
    cudaFuncSetAttribute((const void*)gemm_h<32, __half>, cudaFuncAttributeMaxDynamicSharedMemorySize, SMEM32);

    dim3 tb(32, 8);
    const int mg = B / 128;

    // Launch order chosen so ncu (-s 5 -c 1) profiles the l1 big GEMM (#5).
    transpose_k<<<dim3(H1 / 32, CIN / 32), tb>>>(l1_w, p_l1wt, CIN, H1);      // 0
    {
        size_t n4 = (size_t)B * CIN / 4;
        cvt_h_vec<<<(unsigned)((n4 + 255) / 256), 256>>>(x_feature, p_xfh, n4); // 1
    }
    transpose_k<<<dim3(H2 / 32, H1 / 32), tb>>>(l2_w, p_l2wt, H1, H2);        // 2
    transpose_k<<<dim3(COUT / 32, H2 / 32), tb>>>(l3_w, p_l3wt, H2, COUT);    // 3
    int hblocks = (B * 32 + 255) / 256;
    hyper_hidden<<<hblocks, 256>>>(x_param, hw1_1_w, hw1_1_b, p_h1, B);       // 4

    // 5: the big l1 GEMM — profiled by ncu
    gemm_h<64, __half><<<dim3(H1 / 128, mg), 128, SMEM64>>>(B, H1, CIN, p_xfh, p_l1wt, l1_b, p_x1h);

    hyper_hidden<<<hblocks, 256>>>(x_param, hb1_1_w, hb1_1_b, p_h2, B);
    hyper_hidden<<<hblocks, 256>>>(x_param, hw2_1_w, hw2_1_b, p_h3, B);
    hyper_hidden<<<hblocks, 256>>>(x_param, hb2_1_w, hb2_1_b, p_h4, B);
    transpose_k<<<dim3(H1 / 32, 1), tb>>>(hw1_2_w, p_hw12t, 32, H1);
    transpose_k<<<dim3(H1 / 32, 1), tb>>>(hb1_2_w, p_hb12t, 32, H1);
    transpose_k<<<dim3(H2 / 32, 1), tb>>>(hw2_2_w, p_hw22t, 32, H2);
    transpose_k<<<dim3(H2 / 32, 1), tb>>>(hb2_2_w, p_hb22t, 32, H2);

    // hypernet output layers -> per-sample affine params (fp16)
    gemm_h<32, __half><<<dim3(H1 / 128, mg), 128, SMEM32>>>(B, H1, 32, p_h1, p_hw12t, hw1_2_b, p_w1h);
    gemm_h<32, __half><<<dim3(H1 / 128, mg), 128, SMEM32>>>(B, H1, 32, p_h2, p_hb12t, hb1_2_b, p_b1h);
    gemm_h<32, __half><<<dim3(H2 / 128, mg), 128, SMEM32>>>(B, H2, 32, p_h3, p_hw22t, hw2_2_b, p_w2h);
    gemm_h<32, __half><<<dim3(H2 / 128, mg), 128, SMEM32>>>(B, H2, 32, p_h4, p_hb22t, hb2_2_b, p_b2h);

    // base net (GN in place on fp16 activations)
    gn_affine_relu<H1><<<B, 256>>>(p_x1h, p_w1h, p_b1h);
    gemm_h<64, __half><<<dim3(H2 / 128, mg), 128, SMEM64>>>(B, H2, H1, p_x1h, p_l2wt, l2_b, p_x2h);
    gn_affine_relu<H2><<<B, 256>>>(p_x2h, p_w2h, p_b2h);
    gemm_h<64, float><<<dim3(COUT / 128, mg), 128, SMEM64>>>(B, COUT, H2, p_x2h, p_l3wt, l3_b, p_x3);

    // log_softmax -> output
    logsoftmax256<<<B, 256>>>(p_x3, (float*)d_out);
}